// round 10
// baseline (speedup 1.0000x reference)
#include <cuda_runtime.h>
#include <cuda_fp16.h>
#include <cstdint>

// ---------------------------------------------------------------------------
// BaseLoftqLinear:
//   W' = dequant4(q, s) + 2.0 * (B @ A)      (LoRA folded into weights)
//   out = x @ W'^T + bias
// fp16 mma.sync.m16n8k16 (fp32 accum). Operands pre-packed & pre-swizzled.
// W-prep stages its swizzled tile in smem so gmem stores are fully coalesced.
// ---------------------------------------------------------------------------

#define OUT_F 4096
#define IN_F  4096
#define M_TOK 2048
#define R_LORA 16

// packed 16B-chunk layouts:
//   X: [mt(16)][kt(64)][row(128)][chunk(8)]   chunk stored at (ch ^ (row&7))
//   W: [nt(16)][kt(64)][row(256)][chunk(8)]   chunk stored at (ch ^ (row&7))
__device__ uint4 g_Xp[(size_t)M_TOK * IN_F / 8];   // 16 MB
__device__ uint4 g_Wp[(size_t)OUT_F * IN_F / 8];   // 32 MB

__device__ __forceinline__ uint32_t smem_u32(const void* p) {
    uint32_t a;
    asm("{ .reg .u64 t; cvta.to.shared.u64 t, %1; cvt.u32.u64 %0, t; }"
        : "=r"(a) : "l"(p));
    return a;
}

__device__ __forceinline__ uint32_t h2_u32(__half2 h) {
    union { __half2 h; uint32_t u; } cvt;
    cvt.h = h;
    return cvt.u;
}

// ---------------------------------------------------------------------------
// Prep kernel (fused): blocks 0..1023 = W tiles, 1024..2047 = X tiles.
// ---------------------------------------------------------------------------
__global__ __launch_bounds__(256)
void prep_kernel(const float* __restrict__ x,
                 const int* __restrict__ qweight,
                 const float* __restrict__ scales,
                 const float* __restrict__ lora_A,   // [R, IN_F]
                 const float* __restrict__ lora_B)   // [OUT_F, R]
{
    const int t = threadIdx.x;
    const int b = blockIdx.x;

    if (b < 1024) {
        // ---- W tile: nt = b>>6, kt = b&63; 256 rows x 64 cols ----
        __shared__ float sA[R_LORA][64];     // 4 KB
        __shared__ uint4 sW[256 * 8];        // 32 KB staging (swizzled layout)
        const int nt = b >> 6;
        const int kt = b & 63;

        {
            int r  = t >> 4;
            int c4 = t & 15;
            *(float4*)&sA[r][c4 * 4] =
                *(const float4*)(lora_A + (size_t)r * IN_F + kt * 64 + c4 * 4);
        }
        __syncthreads();

        const int row_g = nt * 256 + t;
        float Bv[R_LORA];
        {
            float4 b0 = *(const float4*)(lora_B + (size_t)row_g * R_LORA + 0);
            float4 b1 = *(const float4*)(lora_B + (size_t)row_g * R_LORA + 4);
            float4 b2 = *(const float4*)(lora_B + (size_t)row_g * R_LORA + 8);
            float4 b3 = *(const float4*)(lora_B + (size_t)row_g * R_LORA + 12);
            Bv[0]=2*b0.x; Bv[1]=2*b0.y; Bv[2]=2*b0.z; Bv[3]=2*b0.w;
            Bv[4]=2*b1.x; Bv[5]=2*b1.y; Bv[6]=2*b1.z; Bv[7]=2*b1.w;
            Bv[8]=2*b2.x; Bv[9]=2*b2.y; Bv[10]=2*b2.z; Bv[11]=2*b2.w;
            Bv[12]=2*b3.x; Bv[13]=2*b3.y; Bv[14]=2*b3.z; Bv[15]=2*b3.w;
        }
        const float s = scales[(size_t)row_g * 64 + kt];
        const float step = 2.0f / 15.0f;

        const uint4* qv = (const uint4*)qweight;

#pragma unroll
        for (int ch = 0; ch < 8; ch++) {
            float l[8] = {0,0,0,0,0,0,0,0};
#pragma unroll
            for (int r = 0; r < R_LORA; r++) {
                float4 a0 = *(const float4*)&sA[r][ch * 8];
                float4 a1 = *(const float4*)&sA[r][ch * 8 + 4];
                l[0] = fmaf(Bv[r], a0.x, l[0]); l[1] = fmaf(Bv[r], a0.y, l[1]);
                l[2] = fmaf(Bv[r], a0.z, l[2]); l[3] = fmaf(Bv[r], a0.w, l[3]);
                l[4] = fmaf(Bv[r], a1.x, l[4]); l[5] = fmaf(Bv[r], a1.y, l[5]);
                l[6] = fmaf(Bv[r], a1.z, l[6]); l[7] = fmaf(Bv[r], a1.w, l[7]);
            }
            uint4 q = qv[(size_t)row_g * 512 + kt * 8 + ch];
            float w[8];
            w[0] = fmaf(fmaf((float)(q.x & 15),        step, -1.0f), s, l[0]);
            w[1] = fmaf(fmaf((float)((q.x >> 4) & 15), step, -1.0f), s, l[1]);
            w[2] = fmaf(fmaf((float)(q.y & 15),        step, -1.0f), s, l[2]);
            w[3] = fmaf(fmaf((float)((q.y >> 4) & 15), step, -1.0f), s, l[3]);
            w[4] = fmaf(fmaf((float)(q.z & 15),        step, -1.0f), s, l[4]);
            w[5] = fmaf(fmaf((float)((q.z >> 4) & 15), step, -1.0f), s, l[5]);
            w[6] = fmaf(fmaf((float)(q.w & 15),        step, -1.0f), s, l[6]);
            w[7] = fmaf(fmaf((float)((q.w >> 4) & 15), step, -1.0f), s, l[7]);

            uint4 o;
            o.x = h2_u32(__floats2half2_rn(w[0], w[1]));
            o.y = h2_u32(__floats2half2_rn(w[2], w[3]));
            o.z = h2_u32(__floats2half2_rn(w[4], w[5]));
            o.w = h2_u32(__floats2half2_rn(w[6], w[7]));
            sW[t * 8 + (ch ^ (t & 7))] = o;    // swizzled into smem staging
        }
        __syncthreads();

        // coalesced copy: consecutive lanes -> consecutive 16B chunks
        uint4* dst = g_Wp + (size_t)b * 2048;
#pragma unroll
        for (int i = 0; i < 8; i++)
            dst[t + i * 256] = sW[t + i * 256];
    } else {
        // ---- X tile: 128 rows x 64 cols (stores already coalesced) ----
        const int bb = b - 1024;
        const int mt = bb >> 6;
        const int kt = bb & 63;
        uint4* dst = g_Xp + (size_t)bb * 1024;
#pragma unroll
        for (int i = 0; i < 4; i++) {
            int c   = t + i * 256;
            int row = c >> 3;
            int ch  = c & 7;
            const float* src = x + ((size_t)(mt * 128 + row)) * IN_F + kt * 64 + ch * 8;
            float4 v0 = *(const float4*)(src);
            float4 v1 = *(const float4*)(src + 4);
            uint4 o;
            o.x = h2_u32(__floats2half2_rn(v0.x, v0.y));
            o.y = h2_u32(__floats2half2_rn(v0.z, v0.w));
            o.z = h2_u32(__floats2half2_rn(v1.x, v1.y));
            o.w = h2_u32(__floats2half2_rn(v1.z, v1.w));
            dst[row * 8 + (ch ^ (row & 7))] = o;
        }
    }
}

// ---------------------------------------------------------------------------
// GEMM: out[M,N] = X @ W'^T + bias   (R8 configuration — fastest measured)
// CTA 128x256, BK=64, 4-stage cp.async, 16 warps (2M x 8N), warp tile 64x32.
// ---------------------------------------------------------------------------
#define BM 128
#define BN 256
#define BK 64
#define NITER (IN_F / BK)              // 64
#define STAGES 4
#define STAGE_CHUNKS 3072              // A 1024 + B 2048 (16B each)
#define SMEM_BYTES (STAGES * STAGE_CHUNKS * 16)   // 196608
#define NTHREADS 512

__device__ __forceinline__ void cp_async16(uint32_t dst, const void* src) {
    asm volatile("cp.async.cg.shared.global [%0], [%1], 16;"
                 :: "r"(dst), "l"(src) : "memory");
}

__device__ __forceinline__ void ldmx4(uint32_t* r, uint32_t addr) {
    asm volatile("ldmatrix.sync.aligned.m8n8.x4.shared.b16 {%0,%1,%2,%3}, [%4];"
                 : "=r"(r[0]), "=r"(r[1]), "=r"(r[2]), "=r"(r[3]) : "r"(addr));
}

__device__ __forceinline__ void mma_f16(float* d, const uint32_t* a,
                                        uint32_t b0, uint32_t b1) {
    asm volatile(
        "mma.sync.aligned.m16n8k16.row.col.f32.f16.f16.f32 "
        "{%0,%1,%2,%3}, {%4,%5,%6,%7}, {%8,%9}, {%0,%1,%2,%3};"
        : "+f"(d[0]), "+f"(d[1]), "+f"(d[2]), "+f"(d[3])
        : "r"(a[0]), "r"(a[1]), "r"(a[2]), "r"(a[3]), "r"(b0), "r"(b1));
}

__global__ __launch_bounds__(NTHREADS, 1)
void gemm_f16_kernel(const float* __restrict__ bias, float* __restrict__ out)
{
    extern __shared__ uint4 smem[];
    const uint32_t sbase = smem_u32(smem);

    const int t    = threadIdx.x;
    const int lane = t & 31;
    const int wid  = t >> 5;           // 0..15
    const int g4   = lane >> 2;
    const int l4   = lane & 3;
    const int wm   = wid & 1;          // 0..1 (M: 64 rows each)
    const int wn   = wid >> 1;         // 0..7 (N: 32 cols each)
    const int mt   = blockIdx.y;
    const int nt   = blockIdx.x;

    // ldmatrix per-lane constants
    const int ar = lane & 7;
    const int ag = lane >> 3;
    const int rg = ag & 1;             // +8 rows
    const int cg = ag >> 1;            // +1 chunk (k+8)
    const uint32_t arow_off = (uint32_t)(wm * 64 + rg * 8 + ar) * 128u;
    const uint32_t brow_off = (uint32_t)(wn * 32 + rg * 8 + ar) * 128u;
    uint32_t sw[4];
#pragma unroll
    for (int ks = 0; ks < 4; ks++)
        sw[ks] = (uint32_t)(((ks * 2 + cg) ^ ar) * 16);

    const uint4* srcA0 = g_Xp + (size_t)mt * 64 * 1024;
    const uint4* srcB0 = g_Wp + (size_t)nt * 64 * 2048;

    float acc[4][4][4];
#pragma unroll
    for (int mf = 0; mf < 4; mf++)
#pragma unroll
        for (int nf = 0; nf < 4; nf++)
#pragma unroll
            for (int j = 0; j < 4; j++) acc[mf][nf][j] = 0.0f;

    auto load_stage = [&](int it, int s) {
        uint4* dst = smem + s * STAGE_CHUNKS;
        const uint4* sa = srcA0 + (size_t)it * 1024;
        const uint4* sb = srcB0 + (size_t)it * 2048;
        uint32_t d = smem_u32(dst);
#pragma unroll
        for (int i = 0; i < 2; i++)
            cp_async16(d + (t + i * NTHREADS) * 16, sa + t + i * NTHREADS);
        d += 1024 * 16;
#pragma unroll
        for (int i = 0; i < 4; i++)
            cp_async16(d + (t + i * NTHREADS) * 16, sb + t + i * NTHREADS);
        asm volatile("cp.async.commit_group;" ::: "memory");
    };

    load_stage(0, 0);
    load_stage(1, 1);
    load_stage(2, 2);

#pragma unroll 1
    for (int it = 0; it < NITER; ++it) {
        if (it < NITER - 2)
            asm volatile("cp.async.wait_group 2;" ::: "memory");
        else if (it == NITER - 2)
            asm volatile("cp.async.wait_group 1;" ::: "memory");
        else
            asm volatile("cp.async.wait_group 0;" ::: "memory");
        __syncthreads();

        if (it + 3 < NITER) load_stage(it + 3, (it + 3) % STAGES);

        const uint32_t aS = sbase + (uint32_t)((it % STAGES) * STAGE_CHUNKS * 16);
        const uint32_t bS = aS + 1024 * 16;

#pragma unroll
        for (int ks = 0; ks < 4; ks++) {
            uint32_t a[4][4], b[2][4];
#pragma unroll
            for (int mf = 0; mf < 4; mf++)
                ldmx4(a[mf], aS + arow_off + mf * 2048 + sw[ks]);
#pragma unroll
            for (int p = 0; p < 2; p++)
                ldmx4(b[p], bS + brow_off + p * 2048 + sw[ks]);

#pragma unroll
            for (int mf = 0; mf < 4; mf++)
#pragma unroll
                for (int p = 0; p < 2; p++) {
                    mma_f16(acc[mf][2 * p],     a[mf], b[p][0], b[p][2]);
                    mma_f16(acc[mf][2 * p + 1], a[mf], b[p][1], b[p][3]);
                }
        }
    }

    // ---- epilogue: bias add + store ----
    const int m0 = mt * BM + wm * 64;
    const int n0 = nt * BN + wn * 32;

    float2 bb[4];
#pragma unroll
    for (int nf = 0; nf < 4; nf++)
        bb[nf] = *(const float2*)(bias + n0 + nf * 8 + l4 * 2);

#pragma unroll
    for (int mf = 0; mf < 4; mf++) {
        const int m = m0 + mf * 16 + g4;
        float* r0 = out + (size_t)m * OUT_F;
        float* r1 = out + (size_t)(m + 8) * OUT_F;
#pragma unroll
        for (int nf = 0; nf < 4; nf++) {
            const int n = n0 + nf * 8 + l4 * 2;
            float2 v0, v1;
            v0.x = acc[mf][nf][0] + bb[nf].x;
            v0.y = acc[mf][nf][1] + bb[nf].y;
            v1.x = acc[mf][nf][2] + bb[nf].x;
            v1.y = acc[mf][nf][3] + bb[nf].y;
            *(float2*)(r0 + n) = v0;
            *(float2*)(r1 + n) = v1;
        }
    }
}

// ---------------------------------------------------------------------------
// Launch: x, qweight, scales, bias, lora_A, lora_B
// ---------------------------------------------------------------------------
extern "C" void kernel_launch(void* const* d_in, const int* in_sizes, int n_in,
                              void* d_out, int out_size)
{
    const float* x      = (const float*)d_in[0];
    const int*   qw     = (const int*)  d_in[1];
    const float* scales = (const float*)d_in[2];
    const float* bias   = (const float*)d_in[3];
    const float* lora_A = (const float*)d_in[4];
    const float* lora_B = (const float*)d_in[5];
    float*       out    = (float*)d_out;
    (void)in_sizes; (void)n_in; (void)out_size;

    cudaFuncSetAttribute(gemm_f16_kernel,
                         cudaFuncAttributeMaxDynamicSharedMemorySize, SMEM_BYTES);

    prep_kernel<<<2048, 256>>>(x, qw, scales, lora_A, lora_B);

    dim3 grid(OUT_F / BN, M_TOK / BM);           // (16, 16)
    gemm_f16_kernel<<<grid, NTHREADS, SMEM_BYTES>>>(bias, out);
}

// round 11
// speedup vs baseline: 1.0324x; 1.0324x over previous
#include <cuda_runtime.h>
#include <cuda_fp16.h>
#include <cstdint>

// ---------------------------------------------------------------------------
// BaseLoftqLinear:
//   W' = dequant4(q, s) + 2.0 * (B @ A)      (LoRA folded into weights)
//   out = x @ W'^T + bias
// fp16 mma.sync.m16n8k16 (fp32 accum). Operands pre-packed & pre-swizzled.
// W-prep LoRA fold in packed half2 (halves the issue count of the fold).
// GEMM config frozen at the measured-best R8 shape (mma.sync rate wall).
// ---------------------------------------------------------------------------

#define OUT_F 4096
#define IN_F  4096
#define M_TOK 2048
#define R_LORA 16

// packed 16B-chunk layouts:
//   X: [mt(16)][kt(64)][row(128)][chunk(8)]   chunk stored at (ch ^ (row&7))
//   W: [nt(16)][kt(64)][row(256)][chunk(8)]   chunk stored at (ch ^ (row&7))
__device__ uint4 g_Xp[(size_t)M_TOK * IN_F / 8];   // 16 MB
__device__ uint4 g_Wp[(size_t)OUT_F * IN_F / 8];   // 32 MB

__device__ __forceinline__ uint32_t smem_u32(const void* p) {
    uint32_t a;
    asm("{ .reg .u64 t; cvta.to.shared.u64 t, %1; cvt.u32.u64 %0, t; }"
        : "=r"(a) : "l"(p));
    return a;
}

__device__ __forceinline__ uint32_t h2_u32(__half2 h) {
    union { __half2 h; uint32_t u; } cvt;
    cvt.h = h;
    return cvt.u;
}

// ---------------------------------------------------------------------------
// Prep kernel (fused): blocks 0..1023 = W tiles, 1024..2047 = X tiles.
// ---------------------------------------------------------------------------
__global__ __launch_bounds__(256)
void prep_kernel(const float* __restrict__ x,
                 const int* __restrict__ qweight,
                 const float* __restrict__ scales,
                 const float* __restrict__ lora_A,   // [R, IN_F]
                 const float* __restrict__ lora_B)   // [OUT_F, R]
{
    const int t = threadIdx.x;
    const int b = blockIdx.x;

    if (b < 1024) {
        // ---- W tile: nt = b>>6, kt = b&63; 256 rows x 64 cols ----
        __shared__ __half2 sA2[R_LORA][32];   // A slice as half2 pairs (2 KB)
        const int nt = b >> 6;
        const int kt = b & 63;

        // stage + convert A slice: 16x64 floats = 256 float4 (one per thread)
        {
            int r  = t >> 4;
            int c4 = t & 15;                  // float4 index within row
            float4 a = *(const float4*)(lora_A + (size_t)r * IN_F + kt * 64 + c4 * 4);
            sA2[r][c4 * 2]     = __floats2half2_rn(a.x, a.y);
            sA2[r][c4 * 2 + 1] = __floats2half2_rn(a.z, a.w);
        }
        __syncthreads();

        const int row_g = nt * 256 + t;
        // 2*B row as half2 broadcasts
        __half2 Bh[R_LORA];
        {
            float4 b0 = *(const float4*)(lora_B + (size_t)row_g * R_LORA + 0);
            float4 b1 = *(const float4*)(lora_B + (size_t)row_g * R_LORA + 4);
            float4 b2 = *(const float4*)(lora_B + (size_t)row_g * R_LORA + 8);
            float4 b3 = *(const float4*)(lora_B + (size_t)row_g * R_LORA + 12);
            Bh[0]  = __float2half2_rn(2.0f * b0.x);
            Bh[1]  = __float2half2_rn(2.0f * b0.y);
            Bh[2]  = __float2half2_rn(2.0f * b0.z);
            Bh[3]  = __float2half2_rn(2.0f * b0.w);
            Bh[4]  = __float2half2_rn(2.0f * b1.x);
            Bh[5]  = __float2half2_rn(2.0f * b1.y);
            Bh[6]  = __float2half2_rn(2.0f * b1.z);
            Bh[7]  = __float2half2_rn(2.0f * b1.w);
            Bh[8]  = __float2half2_rn(2.0f * b2.x);
            Bh[9]  = __float2half2_rn(2.0f * b2.y);
            Bh[10] = __float2half2_rn(2.0f * b2.z);
            Bh[11] = __float2half2_rn(2.0f * b2.w);
            Bh[12] = __float2half2_rn(2.0f * b3.x);
            Bh[13] = __float2half2_rn(2.0f * b3.y);
            Bh[14] = __float2half2_rn(2.0f * b3.z);
            Bh[15] = __float2half2_rn(2.0f * b3.w);
        }
        const float s = scales[(size_t)row_g * 64 + kt];
        const float step = 2.0f / 15.0f;

        const uint4* qv = (const uint4*)qweight;
        uint4* dst = g_Wp + (size_t)b * 2048 + t * 8;

#pragma unroll
        for (int ch = 0; ch < 8; ch++) {
            // LoRA term for 8 cols in half2 (4 accumulators)
            __half2 l2[4];
            l2[0] = __float2half2_rn(0.0f);
            l2[1] = l2[0]; l2[2] = l2[0]; l2[3] = l2[0];
#pragma unroll
            for (int r = 0; r < R_LORA; r++) {
                // one LDS.128 = 8 cols = 4 half2
                uint4 av = *(const uint4*)&sA2[r][ch * 4];
                l2[0] = __hfma2(Bh[r], *(__half2*)&av.x, l2[0]);
                l2[1] = __hfma2(Bh[r], *(__half2*)&av.y, l2[1]);
                l2[2] = __hfma2(Bh[r], *(__half2*)&av.z, l2[2]);
                l2[3] = __hfma2(Bh[r], *(__half2*)&av.w, l2[3]);
            }
            float2 lf0 = __half22float2(l2[0]);
            float2 lf1 = __half22float2(l2[1]);
            float2 lf2 = __half22float2(l2[2]);
            float2 lf3 = __half22float2(l2[3]);

            uint4 q = qv[(size_t)row_g * 512 + kt * 8 + ch];
            float w[8];
            w[0] = fmaf(fmaf((float)(q.x & 15),        step, -1.0f), s, lf0.x);
            w[1] = fmaf(fmaf((float)((q.x >> 4) & 15), step, -1.0f), s, lf0.y);
            w[2] = fmaf(fmaf((float)(q.y & 15),        step, -1.0f), s, lf1.x);
            w[3] = fmaf(fmaf((float)((q.y >> 4) & 15), step, -1.0f), s, lf1.y);
            w[4] = fmaf(fmaf((float)(q.z & 15),        step, -1.0f), s, lf2.x);
            w[5] = fmaf(fmaf((float)((q.z >> 4) & 15), step, -1.0f), s, lf2.y);
            w[6] = fmaf(fmaf((float)(q.w & 15),        step, -1.0f), s, lf3.x);
            w[7] = fmaf(fmaf((float)((q.w >> 4) & 15), step, -1.0f), s, lf3.y);

            uint4 o;
            o.x = h2_u32(__floats2half2_rn(w[0], w[1]));
            o.y = h2_u32(__floats2half2_rn(w[2], w[3]));
            o.z = h2_u32(__floats2half2_rn(w[4], w[5]));
            o.w = h2_u32(__floats2half2_rn(w[6], w[7]));
            dst[ch ^ (t & 7)] = o;
        }
    } else {
        // ---- X tile: 128 rows x 64 cols (stores coalesced per 8-lane group) ----
        const int bb = b - 1024;
        const int mt = bb >> 6;
        const int kt = bb & 63;
        uint4* dst = g_Xp + (size_t)bb * 1024;
#pragma unroll
        for (int i = 0; i < 4; i++) {
            int c   = t + i * 256;
            int row = c >> 3;
            int ch  = c & 7;
            const float* src = x + ((size_t)(mt * 128 + row)) * IN_F + kt * 64 + ch * 8;
            float4 v0 = *(const float4*)(src);
            float4 v1 = *(const float4*)(src + 4);
            uint4 o;
            o.x = h2_u32(__floats2half2_rn(v0.x, v0.y));
            o.y = h2_u32(__floats2half2_rn(v0.z, v0.w));
            o.z = h2_u32(__floats2half2_rn(v1.x, v1.y));
            o.w = h2_u32(__floats2half2_rn(v1.z, v1.w));
            dst[row * 8 + (ch ^ (row & 7))] = o;
        }
    }
}

// ---------------------------------------------------------------------------
// GEMM: out[M,N] = X @ W'^T + bias   (R8 configuration — fastest measured)
// CTA 128x256, BK=64, 4-stage cp.async, 16 warps (2M x 8N), warp tile 64x32.
// ---------------------------------------------------------------------------
#define BM 128
#define BN 256
#define BK 64
#define NITER (IN_F / BK)              // 64
#define STAGES 4
#define STAGE_CHUNKS 3072              // A 1024 + B 2048 (16B each)
#define SMEM_BYTES (STAGES * STAGE_CHUNKS * 16)   // 196608
#define NTHREADS 512

__device__ __forceinline__ void cp_async16(uint32_t dst, const void* src) {
    asm volatile("cp.async.cg.shared.global [%0], [%1], 16;"
                 :: "r"(dst), "l"(src) : "memory");
}

__device__ __forceinline__ void ldmx4(uint32_t* r, uint32_t addr) {
    asm volatile("ldmatrix.sync.aligned.m8n8.x4.shared.b16 {%0,%1,%2,%3}, [%4];"
                 : "=r"(r[0]), "=r"(r[1]), "=r"(r[2]), "=r"(r[3]) : "r"(addr));
}

__device__ __forceinline__ void mma_f16(float* d, const uint32_t* a,
                                        uint32_t b0, uint32_t b1) {
    asm volatile(
        "mma.sync.aligned.m16n8k16.row.col.f32.f16.f16.f32 "
        "{%0,%1,%2,%3}, {%4,%5,%6,%7}, {%8,%9}, {%0,%1,%2,%3};"
        : "+f"(d[0]), "+f"(d[1]), "+f"(d[2]), "+f"(d[3])
        : "r"(a[0]), "r"(a[1]), "r"(a[2]), "r"(a[3]), "r"(b0), "r"(b1));
}

__global__ __launch_bounds__(NTHREADS, 1)
void gemm_f16_kernel(const float* __restrict__ bias, float* __restrict__ out)
{
    extern __shared__ uint4 smem[];
    const uint32_t sbase = smem_u32(smem);

    const int t    = threadIdx.x;
    const int lane = t & 31;
    const int wid  = t >> 5;           // 0..15
    const int g4   = lane >> 2;
    const int l4   = lane & 3;
    const int wm   = wid & 1;          // 0..1 (M: 64 rows each)
    const int wn   = wid >> 1;         // 0..7 (N: 32 cols each)
    const int mt   = blockIdx.y;
    const int nt   = blockIdx.x;

    // ldmatrix per-lane constants
    const int ar = lane & 7;
    const int ag = lane >> 3;
    const int rg = ag & 1;             // +8 rows
    const int cg = ag >> 1;            // +1 chunk (k+8)
    const uint32_t arow_off = (uint32_t)(wm * 64 + rg * 8 + ar) * 128u;
    const uint32_t brow_off = (uint32_t)(wn * 32 + rg * 8 + ar) * 128u;
    uint32_t sw[4];
#pragma unroll
    for (int ks = 0; ks < 4; ks++)
        sw[ks] = (uint32_t)(((ks * 2 + cg) ^ ar) * 16);

    const uint4* srcA0 = g_Xp + (size_t)mt * 64 * 1024;
    const uint4* srcB0 = g_Wp + (size_t)nt * 64 * 2048;

    float acc[4][4][4];
#pragma unroll
    for (int mf = 0; mf < 4; mf++)
#pragma unroll
        for (int nf = 0; nf < 4; nf++)
#pragma unroll
            for (int j = 0; j < 4; j++) acc[mf][nf][j] = 0.0f;

    auto load_stage = [&](int it, int s) {
        uint4* dst = smem + s * STAGE_CHUNKS;
        const uint4* sa = srcA0 + (size_t)it * 1024;
        const uint4* sb = srcB0 + (size_t)it * 2048;
        uint32_t d = smem_u32(dst);
#pragma unroll
        for (int i = 0; i < 2; i++)
            cp_async16(d + (t + i * NTHREADS) * 16, sa + t + i * NTHREADS);
        d += 1024 * 16;
#pragma unroll
        for (int i = 0; i < 4; i++)
            cp_async16(d + (t + i * NTHREADS) * 16, sb + t + i * NTHREADS);
        asm volatile("cp.async.commit_group;" ::: "memory");
    };

    load_stage(0, 0);
    load_stage(1, 1);
    load_stage(2, 2);

#pragma unroll 1
    for (int it = 0; it < NITER; ++it) {
        if (it < NITER - 2)
            asm volatile("cp.async.wait_group 2;" ::: "memory");
        else if (it == NITER - 2)
            asm volatile("cp.async.wait_group 1;" ::: "memory");
        else
            asm volatile("cp.async.wait_group 0;" ::: "memory");
        __syncthreads();

        if (it + 3 < NITER) load_stage(it + 3, (it + 3) % STAGES);

        const uint32_t aS = sbase + (uint32_t)((it % STAGES) * STAGE_CHUNKS * 16);
        const uint32_t bS = aS + 1024 * 16;

#pragma unroll
        for (int ks = 0; ks < 4; ks++) {
            uint32_t a[4][4], b[2][4];
#pragma unroll
            for (int mf = 0; mf < 4; mf++)
                ldmx4(a[mf], aS + arow_off + mf * 2048 + sw[ks]);
#pragma unroll
            for (int p = 0; p < 2; p++)
                ldmx4(b[p], bS + brow_off + p * 2048 + sw[ks]);

#pragma unroll
            for (int mf = 0; mf < 4; mf++)
#pragma unroll
                for (int p = 0; p < 2; p++) {
                    mma_f16(acc[mf][2 * p],     a[mf], b[p][0], b[p][2]);
                    mma_f16(acc[mf][2 * p + 1], a[mf], b[p][1], b[p][3]);
                }
        }
    }

    // ---- epilogue: bias add + store ----
    const int m0 = mt * BM + wm * 64;
    const int n0 = nt * BN + wn * 32;

    float2 bb[4];
#pragma unroll
    for (int nf = 0; nf < 4; nf++)
        bb[nf] = *(const float2*)(bias + n0 + nf * 8 + l4 * 2);

#pragma unroll
    for (int mf = 0; mf < 4; mf++) {
        const int m = m0 + mf * 16 + g4;
        float* r0 = out + (size_t)m * OUT_F;
        float* r1 = out + (size_t)(m + 8) * OUT_F;
#pragma unroll
        for (int nf = 0; nf < 4; nf++) {
            const int n = n0 + nf * 8 + l4 * 2;
            float2 v0, v1;
            v0.x = acc[mf][nf][0] + bb[nf].x;
            v0.y = acc[mf][nf][1] + bb[nf].y;
            v1.x = acc[mf][nf][2] + bb[nf].x;
            v1.y = acc[mf][nf][3] + bb[nf].y;
            *(float2*)(r0 + n) = v0;
            *(float2*)(r1 + n) = v1;
        }
    }
}

// ---------------------------------------------------------------------------
// Launch: x, qweight, scales, bias, lora_A, lora_B
// ---------------------------------------------------------------------------
extern "C" void kernel_launch(void* const* d_in, const int* in_sizes, int n_in,
                              void* d_out, int out_size)
{
    const float* x      = (const float*)d_in[0];
    const int*   qw     = (const int*)  d_in[1];
    const float* scales = (const float*)d_in[2];
    const float* bias   = (const float*)d_in[3];
    const float* lora_A = (const float*)d_in[4];
    const float* lora_B = (const float*)d_in[5];
    float*       out    = (float*)d_out;
    (void)in_sizes; (void)n_in; (void)out_size;

    cudaFuncSetAttribute(gemm_f16_kernel,
                         cudaFuncAttributeMaxDynamicSharedMemorySize, SMEM_BYTES);

    prep_kernel<<<2048, 256>>>(x, qw, scales, lora_A, lora_B);

    dim3 grid(OUT_F / BN, M_TOK / BM);           // (16, 16)
    gemm_f16_kernel<<<grid, NTHREADS, SMEM_BYTES>>>(bias, out);
}